// round 16
// baseline (speedup 1.0000x reference)
#include <cuda_runtime.h>
#include <cstdint>

// Problem shape (fixed for this dataset entry)
#define B_  4
#define C_  32
#define H_  256
#define W_  512
#define D_  48
#define HW_ (H_ * W_)

#define WT  128              // w-tile per block
#define NTHREADS 256
#define MB  8                // m16-blocks per tile (one per warp)
#define KS  8                // k-steps (k8) per m-block: band 16+48 = 64 = 8*8
#define KCH 22               // distinct k8 chunks in window [0, 176)

// smem (dynamic): A-frag 8192 words + B-frag 5632 words = 55296 B -> 4 CTAs/SM
#define A_FLOATS 8192        // [MB][KS][128 words], XOR-16 swizzled
#define B_STRIDE 8           // words per (chunk, lane) row, XOR-4 swizzled
#define B_FLOATS (KCH * 32 * B_STRIDE)   // 5632
#define SMEM_BYTES ((A_FLOATS + B_FLOATS) * 4)

// fp32 -> tf32 (round-to-nearest) kept in b32 register
__device__ __forceinline__ unsigned tf32_of(float v) {
    unsigned r;
    asm("cvt.rna.tf32.f32 %0, %1;" : "=r"(r) : "f"(v));
    return r;
}

// D(16x8,f32) += A(16x8,tf32,row) * B(8x8,tf32,col)
__device__ __forceinline__ void mma8(float* d,
                                     unsigned a0, unsigned a1,
                                     unsigned a2, unsigned a3,
                                     unsigned b0, unsigned b1) {
    asm volatile(
        "mma.sync.aligned.m16n8k8.row.col.f32.tf32.tf32.f32 "
        "{%0,%1,%2,%3}, {%4,%5,%6,%7}, {%8,%9}, {%0,%1,%2,%3};"
        : "+f"(d[0]), "+f"(d[1]), "+f"(d[2]), "+f"(d[3])
        : "r"(a0), "r"(a1), "r"(a2), "r"(a3), "r"(b0), "r"(b1));
}

__global__ void __launch_bounds__(NTHREADS, 4)
dense_warp_kernel(const float* __restrict__ h1,
                  const float* __restrict__ cost,
                  float* __restrict__ out) {
    extern __shared__ __align__(16) unsigned smu[];
    unsigned* Af = smu;                // A-frag region (swizzled)
    unsigned* Bf = smu + A_FLOATS;     // B-frag region (swizzled)

    const int bx    = blockIdx.x;
    const int wt    = bx & 3;                 // W_/WT = 4 tiles
    const int h     = (bx >> 2) & (H_ - 1);
    const int b     = bx >> 10;               // /(4*256)
    const int wbase = wt * WT;
    const int tid   = threadIdx.x;

    const float* cbase = cost + ((size_t)(b * D_) * H_ + h) * W_ + wbase;
    const float* hbase = h1   + ((size_t)(b * C_) * H_ + h) * W_ + wbase;

    // ---- 1. zero A (covers out-of-band slots; swizzle-invariant) ----
    {
        uint4 z = make_uint4(0u, 0u, 0u, 0u);
        #pragma unroll
        for (int i = 0; i < A_FLOATS / 4 / NTHREADS; i++)     // 8 iters
            ((uint4*)Af)[i * NTHREADS + tid] = z;
    }
    __syncthreads();

    // ---- 2. A band fill, vectorized (tid < 192) ----
    // thread (d = tid>>2, q = tid&3) loads 8x LDG.128 over mb, scattering
    // 4 tf32 words each to precomputed swizzled bases + mb*1024 immediates.
    // A-word layout per (mb,ks) 128-word block: idx = L*4 + slot,
    //   L = g*4+t, slot = hi + 2*bit2;  phys = idx ^ (16*((L>>4)&1)).
    // STS banks verified distinct across the warp for each u.
    if (tid < 192) {
        const int d = tid >> 2, q = tid & 3;
        const float4* src = (const float4*)(cbase + (size_t)d * HW_) + q;

        int basew[4];
        #pragma unroll
        for (int u = 0; u < 4; u++) {
            int jj = 4 * q + u;
            int kk = d + jj;                 // <= 62, always in-band
            int t = kk & 3, bit2 = (kk >> 2) & 1, ks = kk >> 3;
            int g = jj & 7, hi = jj >> 3;
            int L = g * 4 + t;
            int idx = L * 4 + hi + 2 * bit2;
            basew[u] = ks * 128 + (idx ^ (16 * ((L >> 4) & 1)));
        }
        #pragma unroll
        for (int mb = 0; mb < MB; mb++) {
            float4 v = src[mb * 4];          // 16 consecutive floats of row d
            Af[mb * 1024 + basew[0]] = tf32_of(v.x);
            Af[mb * 1024 + basew[1]] = tf32_of(v.y);
            Af[mb * 1024 + basew[2]] = tf32_of(v.z);
            Af[mb * 1024 + basew[3]] = tf32_of(v.w);
        }
    }

    // ---- 3. B fill (scalar, strength-reduced; XOR-4 word swizzle) ----
    // B[k][c] = tf32(h1[c][wbase+k]) (0 beyond W); thread owns fixed (c,k8).
    // storage: chunk*256 + L*8 + ((2nt+j) ^ (4*(g&1))),
    //   L = (c&7)*4 + (k8&3), j = k8>>2, nt = c>>3.
    {
        const int c  = tid >> 3;             // 0..31
        const int k8 = tid & 7;
        const int t = k8 & 3, j = k8 >> 2, g = c & 7, nt = c >> 3;
        unsigned* bdst = Bf + (g * 4 + t) * B_STRIDE
                            + ((2 * nt + j) ^ (4 * (g & 1)));
        const float* lsrc = hbase + (size_t)c * HW_ + k8;
        const int klim = W_ - wbase - k8;    // ch*8 < klim -> in bounds

        #pragma unroll
        for (int ch = 0; ch < KCH; ch++) {
            float fv = (ch * 8 < klim) ? lsrc[ch * 8] : 0.0f;
            bdst[ch * (32 * B_STRIDE)] = tf32_of(fv);
        }
    }
    __syncthreads();

    // ---- 4. mainloop: warp wid owns m-block wid (w rows 16*wid..+15) ----
    const int lane = tid & 31;
    const int wid  = tid >> 5;               // 0..7

    float acc[16];
    #pragma unroll
    for (int i = 0; i < 16; i++) acc[i] = 0.0f;

    // A read: swizzled uint4 index lane' = lane ^ ((lane&16)>>2)
    const int laneA = lane ^ ((lane & 16) >> 2);
    const uint4* Ald = (const uint4*)Af + (wid * 8) * 32 + laneA;

    // B read: lane row at lane*8 words; lo uint4 at +Xb, hi at +(Xb^4)
    const int Xb = lane & 4;
    const unsigned* Brow = Bf + (2 * wid) * (32 * B_STRIDE) + lane * 8;

    #pragma unroll
    for (int ks = 0; ks < KS; ks++) {
        uint4 a  = Ald[ks * 32];                               // LDS.128
        uint4 b0 = *(const uint4*)(Brow + ks * 256 + Xb);       // logical 0..3
        uint4 b1 = *(const uint4*)(Brow + ks * 256 + (Xb ^ 4)); // logical 4..7
        mma8(acc + 0,  a.x, a.y, a.z, a.w, b0.x, b0.y);
        mma8(acc + 4,  a.x, a.y, a.z, a.w, b0.z, b0.w);
        mma8(acc + 8,  a.x, a.y, a.z, a.w, b1.x, b1.y);
        mma8(acc + 12, a.x, a.y, a.z, a.w, b1.z, b1.w);
    }

    // ---- 5. epilogue: D[g][2t] layout -> out[c][w] scatter ----
    {
        const int g = lane >> 2, t = lane & 3;
        const int w = wbase + wid * 16 + g;
        float* obase = out + ((size_t)(b * C_) * H_ + h) * W_;
        #pragma unroll
        for (int nt = 0; nt < 4; nt++) {
            int c = nt * 8 + t * 2;
            float* p = obase + (size_t)c * HW_ + w;
            p[0]       = acc[nt * 4 + 0];
            p[HW_]     = acc[nt * 4 + 1];
            p[8]       = acc[nt * 4 + 2];
            p[HW_ + 8] = acc[nt * 4 + 3];
        }
    }
}

extern "C" void kernel_launch(void* const* d_in, const int* in_sizes, int n_in,
                              void* d_out, int out_size) {
    (void)in_sizes; (void)n_in; (void)out_size;
    const float* h1   = (const float*)d_in[0];
    const float* cost = (const float*)d_in[1];
    float* out        = (float*)d_out;

    // >48KB static limit -> dynamic smem (attribute set is idempotent,
    // not a stream op, and performs no allocation)
    cudaFuncSetAttribute(dense_warp_kernel,
                         cudaFuncAttributeMaxDynamicSharedMemorySize,
                         SMEM_BYTES);

    const int nblocks = B_ * H_ * (W_ / WT);   // 4096
    dense_warp_kernel<<<nblocks, NTHREADS, SMEM_BYTES>>>(h1, cost, out);
}

// round 17
// speedup vs baseline: 1.2915x; 1.2915x over previous
#include <cuda_runtime.h>
#include <cstdint>

// Problem shape (fixed for this dataset entry)
#define B_  4
#define C_  32
#define H_  256
#define W_  512
#define D_  48
#define HW_ (H_ * W_)

#define WT  256              // w-tile per block
#define NTHREADS 512
#define MB  16               // m16-blocks per tile (one per warp)
#define KS  8                // k-steps (k8) per m-block: band 16+48 = 64 = 8*8
#define KCH 38               // distinct k8 chunks in window [0, 304)

// smem (dynamic): A-frag 16384 words + B-frag 10944 words = 109312 B -> 2 CTAs/SM
#define A_FLOATS 16384       // [MB][KS][32 lanes][4 slots]  (R13 layout, unchanged)
#define B_STRIDE 9           // words per (chunk, lane) row: 8 used + 1 pad (R13)
#define B_FLOATS (KCH * 32 * B_STRIDE)   // 10944
#define SMEM_BYTES ((A_FLOATS + B_FLOATS) * 4)

// fp32 -> tf32 (round-to-nearest) kept in b32 register
__device__ __forceinline__ unsigned tf32_of(float v) {
    unsigned r;
    asm("cvt.rna.tf32.f32 %0, %1;" : "=r"(r) : "f"(v));
    return r;
}

// D(16x8,f32) += A(16x8,tf32,row) * B(8x8,tf32,col)
__device__ __forceinline__ void mma8(float* d,
                                     unsigned a0, unsigned a1,
                                     unsigned a2, unsigned a3,
                                     unsigned b0, unsigned b1) {
    asm volatile(
        "mma.sync.aligned.m16n8k8.row.col.f32.tf32.tf32.f32 "
        "{%0,%1,%2,%3}, {%4,%5,%6,%7}, {%8,%9}, {%0,%1,%2,%3};"
        : "+f"(d[0]), "+f"(d[1]), "+f"(d[2]), "+f"(d[3])
        : "r"(a0), "r"(a1), "r"(a2), "r"(a3), "r"(b0), "r"(b1));
}

__global__ void __launch_bounds__(NTHREADS, 2)
dense_warp_kernel(const float* __restrict__ h1,
                  const float* __restrict__ cost,
                  float* __restrict__ out) {
    extern __shared__ __align__(16) unsigned smu[];
    unsigned* Af = smu;                // A-frag region
    unsigned* Bf = smu + A_FLOATS;     // B-frag region

    const int bx    = blockIdx.x;
    const int wt    = bx & 1;                 // W_/WT = 2 tiles
    const int h     = (bx >> 1) & (H_ - 1);
    const int b     = bx >> 9;                // /(2*256)
    const int wbase = wt * WT;
    const int tid   = threadIdx.x;

    const float* cbase = cost + ((size_t)(b * D_) * H_ + h) * W_ + wbase;
    const float* hbase = h1   + ((size_t)(b * C_) * H_ + h) * W_ + wbase;

    // ---- 1. zero A (covers out-of-band slots) ----
    {
        uint4 z = make_uint4(0u, 0u, 0u, 0u);
        #pragma unroll
        for (int i = 0; i < A_FLOATS / 4 / NTHREADS; i++)     // 8 iters
            ((uint4*)Af)[i * NTHREADS + tid] = z;
    }
    __syncthreads();

    // ---- 2. A band fill (R14 strength-reduced, extended to MB=16) ----
    // A-block[mb][jj][kk] = tf32(cost[d][wbase + 16*mb + jj]), kk = jj + d,
    // d = dd*16 + seg.  t/bit2 are dd-invariant, ks = ks0 + 2*dd, so each
    // iter = LDG[imm] + CVT + STS[imm].  Thread = (jj, seg, mh); mh picks
    // the mb half.
    {
        const int jj  = tid & 15;
        const int seg = (tid >> 4) & 15;     // d = dd*16 + seg
        const int mh  = tid >> 8;            // 0..1 -> mb = mh*8 + mbi
        const int kk0  = jj + seg;
        const int t    = kk0 & 3;
        const int bit2 = (kk0 >> 2) & 1;
        const int ks0  = kk0 >> 3;           // +2 per dd
        const int g    = jj & 7, hi = jj >> 3;
        unsigned* abase =
            Af + (ks0 * 32 + g * 4 + t) * 4 + hi + 2 * bit2 + mh * (8 * 1024);
        const float* lbase = cbase + (size_t)seg * HW_ + mh * 128 + jj;

        #pragma unroll
        for (int mbi = 0; mbi < 8; mbi++) {
            #pragma unroll
            for (int dd = 0; dd < 3; dd++) {
                unsigned v = tf32_of(lbase[(size_t)dd * (16 * HW_) + mbi * 16]);
                abase[mbi * 1024 + dd * 256] = v;
            }
        }
    }

    // ---- 3. B fill (strength-reduced; stride-9 layout, unchanged) ----
    // B[k][c] = tf32(h1[c][wbase+k]) (0 beyond W); thread owns (c, k16),
    // k = k16 + 16*ch, ch = 0..18 -> chunk index = (k16>>3) + 2*ch.
    // frag addr = chunk*288 + (g*4+t)*9 + 2*nt + j  (t=k16&3, j=(k16>>2)&1)
    {
        const int c   = tid >> 4;            // 0..31
        const int k16 = tid & 15;            // 0..15
        const int t = k16 & 3, j = (k16 >> 2) & 1, g = c & 7, nt = c >> 3;
        unsigned* bdst = Bf + (k16 >> 3) * 288 + (g * 4 + t) * B_STRIDE
                            + 2 * nt + j;
        const float* lsrc = hbase + (size_t)c * HW_ + k16;
        const int klim = W_ - wbase - k16;   // 16*ch < klim -> in bounds

        #pragma unroll
        for (int ch = 0; ch < 19; ch++) {    // covers k = 0..303
            float fv = (16 * ch < klim) ? lsrc[ch * 16] : 0.0f;
            bdst[ch * 576] = tf32_of(fv);
        }
    }
    __syncthreads();

    // ---- 4. mainloop: warp wid owns m-block wid (w rows 16*wid..+15) ----
    const int lane = tid & 31;
    const int wid  = tid >> 5;               // 0..15

    float acc[16];
    #pragma unroll
    for (int i = 0; i < 16; i++) acc[i] = 0.0f;

    const uint4*    Ald = (const uint4*)Af + (wid * 8) * 32 + lane;
    const unsigned* Bld = Bf + lane * B_STRIDE;

    #pragma unroll
    for (int ks = 0; ks < KS; ks++) {
        uint4 a = Ald[ks * 32];                          // LDS.128, lane-major
        const unsigned* bp = Bld + (2 * wid + ks) * 288; // chunk = kbase/8
        #pragma unroll
        for (int nt = 0; nt < 4; nt++) {
            unsigned b0 = bp[2 * nt + 0];
            unsigned b1 = bp[2 * nt + 1];
            mma8(acc + nt * 4, a.x, a.y, a.z, a.w, b0, b1);
        }
    }

    // ---- 5. epilogue: D[g][2t] layout -> out[c][w] scatter ----
    // d0:(w=+g, c), d1:(+g, c+1), d2:(+g+8, c), d3:(+g+8, c+1)
    {
        const int g = lane >> 2, t = lane & 3;
        const int w = wbase + wid * 16 + g;
        float* obase = out + ((size_t)(b * C_) * H_ + h) * W_;
        #pragma unroll
        for (int nt = 0; nt < 4; nt++) {
            int c = nt * 8 + t * 2;
            float* p = obase + (size_t)c * HW_ + w;
            p[0]       = acc[nt * 4 + 0];
            p[HW_]     = acc[nt * 4 + 1];
            p[8]       = acc[nt * 4 + 2];
            p[HW_ + 8] = acc[nt * 4 + 3];
        }
    }
}

extern "C" void kernel_launch(void* const* d_in, const int* in_sizes, int n_in,
                              void* d_out, int out_size) {
    (void)in_sizes; (void)n_in; (void)out_size;
    const float* h1   = (const float*)d_in[0];
    const float* cost = (const float*)d_in[1];
    float* out        = (float*)d_out;

    // >48KB static limit -> dynamic smem (attribute set is idempotent,
    // not a stream op, and performs no allocation)
    cudaFuncSetAttribute(dense_warp_kernel,
                         cudaFuncAttributeMaxDynamicSharedMemorySize,
                         SMEM_BYTES);

    const int nblocks = B_ * H_ * (W_ / WT);   // 2048
    dense_warp_kernel<<<nblocks, NTHREADS, SMEM_BYTES>>>(h1, cost, out);
}